// round 8
// baseline (speedup 1.0000x reference)
#include <cuda_runtime.h>
#include <cuda_fp16.h>
#include <math.h>

#define NN      4096
#define IN_DIM  128
#define HEADS   4
#define OUT_DIM 64
#define HD      256   // HEADS*OUT_DIM
#define NB      512   // gather chunk size
#define NBP     (NB + 8)
#define SEG     1024  // csr segment length (ints)

// persistent scratch (allocation-free rule: __device__ globals)
__device__ uint4          g_hb[NN * 32];           // h in fp16: 4096 x 256 x 2B = 2 MB
__device__ float          g_si[NN * HEADS];
__device__ float          g_sj[NN * HEADS];
__device__ float          g_mx[HEADS];
__device__ unsigned short g_nbr[(size_t)NN * NN];  // 4 segments of 1024 per row
__device__ int            g_cnt4[NN * 4];

// --------------------------------------------------------------------------
// Fat kernel: bid%17==0 -> gemm (128 blocks, 32 rows each, W smem-tiled)
//             else      -> csr  (2048 blocks, 1 warp = 1 segment, MLP=8)
// --------------------------------------------------------------------------
__global__ __launch_bounds__(256) void fat_kernel(const float* __restrict__ x,
                                                  const float* __restrict__ W,
                                                  const float* __restrict__ a_src,
                                                  const float* __restrict__ a_dst,
                                                  const int* __restrict__ mask) {
    __shared__ float xs[32][IN_DIM];     // 16 KB
    __shared__ float Wt[16 * HD];        // 16 KB (k-chunk of W)
    __shared__ float s_si[32][HEADS];
    __shared__ float s_sj[32][HEADS];
    const int t   = threadIdx.x;
    const int bid = blockIdx.x;

    if (bid % 17 == 0) {
        // ================= GEMM part =================
        const int row0 = (bid / 17) * 32;
        const float4* x4 = (const float4*)(x + row0 * IN_DIM);
        float4* xs4 = (float4*)xs;
#pragma unroll
        for (int i = 0; i < 4; i++) xs4[t + i * 256] = x4[t + i * 256];
        if (t < 128) { s_si[t >> 2][t & 3] = 0.f; s_sj[t >> 2][t & 3] = 0.f; }

        const int slot = t & 63;   // float4 column (dims slot*4..+3)
        const int grp  = t >> 6;   // 4 groups of 8 rows
        float4 acc[8];
#pragma unroll
        for (int r = 0; r < 8; r++) acc[r] = make_float4(0.f, 0.f, 0.f, 0.f);

        const float4* W4  = (const float4*)W;
        float4*       Wt4 = (float4*)Wt;
#pragma unroll
        for (int kc = 0; kc < 8; kc++) {
            __syncthreads();
#pragma unroll
            for (int i = 0; i < 4; i++)
                Wt4[t + i * 256] = W4[kc * 16 * 64 + t + i * 256];
            __syncthreads();
#pragma unroll
            for (int k2 = 0; k2 < 16; k2++) {
                float4 wv = Wt4[k2 * 64 + slot];
#pragma unroll
                for (int r = 0; r < 8; r++) {
                    float xv = xs[grp * 8 + r][kc * 16 + k2];
                    acc[r].x = fmaf(xv, wv.x, acc[r].x);
                    acc[r].y = fmaf(xv, wv.y, acc[r].y);
                    acc[r].z = fmaf(xv, wv.z, acc[r].z);
                    acc[r].w = fmaf(xv, wv.w, acc[r].w);
                }
            }
        }
        // fp16 h store + fused score epilogue
        __half2* HB = (__half2*)g_hb;
        const int d0 = (slot * 4) & 63;
        const int hh = slot >> 4;
        float as0 = a_src[d0], as1 = a_src[d0 + 1], as2 = a_src[d0 + 2], as3 = a_src[d0 + 3];
        float ad0 = a_dst[d0], ad1 = a_dst[d0 + 1], ad2 = a_dst[d0 + 2], ad3 = a_dst[d0 + 3];
#pragma unroll
        for (int r = 0; r < 8; r++) {
            int row = row0 + grp * 8 + r;
            HB[(size_t)row * 128 + slot * 2]     = __floats2half2_rn(acc[r].x, acc[r].y);
            HB[(size_t)row * 128 + slot * 2 + 1] = __floats2half2_rn(acc[r].z, acc[r].w);
            float psi = acc[r].x * as0 + acc[r].y * as1 + acc[r].z * as2 + acc[r].w * as3;
            float psj = acc[r].x * ad0 + acc[r].y * ad1 + acc[r].z * ad2 + acc[r].w * ad3;
            atomicAdd(&s_si[grp * 8 + r][hh], psi);
            atomicAdd(&s_sj[grp * 8 + r][hh], psj);
        }
        __syncthreads();
        if (t < 128) {
            g_si[(row0 + (t >> 2)) * HEADS + (t & 3)] = s_si[t >> 2][t & 3];
            g_sj[(row0 + (t >> 2)) * HEADS + (t & 3)] = s_sj[t >> 2][t & 3];
        }
    } else {
        // ================= CSR part: 1 warp = 1 segment of 1024 ints =======
        const int csrIdx = bid - (bid / 17) - 1;         // 0..2047
        const int warp = t >> 5, lane = t & 31;
        const int segIdx = csrIdx * 8 + warp;            // 0..16383
        const int row = segIdx >> 2, seg = segIdx & 3;

        const int4* m4 = (const int4*)mask + (size_t)row * (NN / 4) + seg * 256;
        unsigned short* dst = g_nbr + (size_t)row * NN + seg * SEG;

        int4 v[8];
#pragma unroll
        for (int it = 0; it < 8; it++) v[it] = m4[it * 32 + lane];   // MLP=8

        int base = 0;
        const int jb0 = seg * SEG;
#pragma unroll
        for (int it = 0; it < 8; it++) {
            int b0 = (v[it].x != 0), b1 = (v[it].y != 0);
            int b2 = (v[it].z != 0), b3 = (v[it].w != 0);
            int mycnt = b0 + b1 + b2 + b3;
            int incl = mycnt;
#pragma unroll
            for (int d = 1; d < 32; d <<= 1) {
                int nn = __shfl_up_sync(0xffffffffu, incl, d);
                if (lane >= d) incl += nn;
            }
            int total = __shfl_sync(0xffffffffu, incl, 31);
            int off = incl - mycnt;
            int jb  = jb0 + (it * 32 + lane) * 4;
            int pos = base + off;
            if (b0) dst[pos++] = (unsigned short)(jb);
            if (b1) dst[pos++] = (unsigned short)(jb + 1);
            if (b2) dst[pos++] = (unsigned short)(jb + 2);
            if (b3) dst[pos++] = (unsigned short)(jb + 3);
            base += total;
        }
        if (lane == 0) g_cnt4[segIdx] = base;
    }
}

// --------------------------------------------------------------------------
// Kernel 2: g_mx[h] = max_n g_sj[n][h]. One block.
// --------------------------------------------------------------------------
__global__ __launch_bounds__(256) void max_sj_kernel() {
    __shared__ float red[HEADS][8];
    const int t = threadIdx.x, lane = t & 31, wid = t >> 5;
    float mx[HEADS];
#pragma unroll
    for (int h = 0; h < HEADS; h++) mx[h] = -INFINITY;
    const float4* s4 = (const float4*)g_sj;
    for (int i = t; i < NN; i += 256) {
        float4 v = s4[i];
        mx[0] = fmaxf(mx[0], v.x); mx[1] = fmaxf(mx[1], v.y);
        mx[2] = fmaxf(mx[2], v.z); mx[3] = fmaxf(mx[3], v.w);
    }
#pragma unroll
    for (int h = 0; h < HEADS; h++)
#pragma unroll
        for (int d = 16; d; d >>= 1)
            mx[h] = fmaxf(mx[h], __shfl_xor_sync(0xffffffffu, mx[h], d));
    if (lane == 0)
#pragma unroll
        for (int h = 0; h < HEADS; h++) red[h][wid] = mx[h];
    __syncthreads();
    if (t < HEADS) {
        float m = red[t][0];
#pragma unroll
        for (int w = 1; w < 8; w++) m = fmaxf(m, red[t][w]);
        g_mx[t] = m;
    }
}

// --------------------------------------------------------------------------
// Kernel 3: sparse gather attention (R6 shape: NB=512, ~24.7KB smem).
// --------------------------------------------------------------------------
__global__ __launch_bounds__(256) void gather_kernel(float* __restrict__ out) {
    __shared__ unsigned short nbr[NN];          // 8 KB
    __shared__ float p_sh[HEADS][NBP];          // 8.3 KB
    __shared__ float acc_sh[8][32][8];          // 8 KB
    __shared__ float red_sh[HEADS][8];
    __shared__ float tot_sh[HEADS];

    const int t    = threadIdx.x;
    const int lane = t & 31;
    const int wid  = t >> 5;
    const int row  = blockIdx.x;
    const int c    = t & 31;      // 16B chunk of the 512B fp16 row
    const int q    = t >> 5;      // j-subslot (warp)
    const int hc   = c >> 3;      // head owned in acc pass

    // ---- stage + compact 4 segments ----
    int c4[4];
#pragma unroll
    for (int s = 0; s < 4; s++) c4[s] = g_cnt4[row * 4 + s];
    int o1 = c4[0], o2 = o1 + c4[1], o3 = o2 + c4[2];
    int cnt = o3 + c4[3];
    const unsigned short* nrow = g_nbr + (size_t)row * NN;
    const bool uniform = (cnt == 0);
    if (uniform) {
        for (int jj = t; jj < NN; jj += 256) nbr[jj] = (unsigned short)jj;
        cnt = NN;
    } else {
        for (int jj = t; jj < c4[0]; jj += 256) nbr[jj]      = nrow[jj];
        for (int jj = t; jj < c4[1]; jj += 256) nbr[o1 + jj] = nrow[SEG + jj];
        for (int jj = t; jj < c4[2]; jj += 256) nbr[o2 + jj] = nrow[2 * SEG + jj];
        for (int jj = t; jj < c4[3]; jj += 256) nbr[o3 + jj] = nrow[3 * SEG + jj];
    }

    // ---- per-row factors ----
    float si[HEADS], m[HEADS];
#pragma unroll
    for (int h = 0; h < HEADS; h++) {
        si[h] = g_si[row * HEADS + h];
        float v = si[h] + g_mx[h];
        m[h] = fmaxf(v, 0.2f * v);        // lrelu, >= all row scores
    }
    float sum[HEADS] = {0.f, 0.f, 0.f, 0.f};
    float acc[8] = {0.f, 0.f, 0.f, 0.f, 0.f, 0.f, 0.f, 0.f};

    const float4* gsj4 = (const float4*)g_sj;
    __syncthreads();

    for (int base = 0; base < cnt; base += NB) {
        const int cn = min(NB, cnt - base);

        // ---- p-pass ----
        for (int jj = t; jj < cn; jj += 256) {
            float4 sj = gsj4[nbr[base + jj]];
            float e0 = si[0] + sj.x; e0 = fmaxf(e0, 0.2f * e0);
            float e1 = si[1] + sj.y; e1 = fmaxf(e1, 0.2f * e1);
            float e2 = si[2] + sj.z; e2 = fmaxf(e2, 0.2f * e2);
            float e3 = si[3] + sj.w; e3 = fmaxf(e3, 0.2f * e3);
            float p0 = uniform ? 1.f : __expf(e0 - m[0]);
            float p1 = uniform ? 1.f : __expf(e1 - m[1]);
            float p2 = uniform ? 1.f : __expf(e2 - m[2]);
            float p3 = uniform ? 1.f : __expf(e3 - m[3]);
            p_sh[0][jj] = p0; p_sh[1][jj] = p1;
            p_sh[2][jj] = p2; p_sh[3][jj] = p3;
            sum[0] += p0; sum[1] += p1; sum[2] += p2; sum[3] += p3;
        }
        __syncthreads();

        // ---- acc-pass: fp16 h rows, warp covers full 512B row per edge ----
#pragma unroll 8
        for (int jj = q; jj < cn; jj += 8) {
            int j = nbr[base + jj];
            float pv = p_sh[hc][jj];
            uint4 hv = g_hb[(size_t)j * 32 + c];
            float2 f0 = __half22float2(*(__half2*)&hv.x);
            float2 f1 = __half22float2(*(__half2*)&hv.y);
            float2 f2 = __half22float2(*(__half2*)&hv.z);
            float2 f3 = __half22float2(*(__half2*)&hv.w);
            acc[0] = fmaf(pv, f0.x, acc[0]);
            acc[1] = fmaf(pv, f0.y, acc[1]);
            acc[2] = fmaf(pv, f1.x, acc[2]);
            acc[3] = fmaf(pv, f1.y, acc[3]);
            acc[4] = fmaf(pv, f2.x, acc[4]);
            acc[5] = fmaf(pv, f2.y, acc[5]);
            acc[6] = fmaf(pv, f3.x, acc[6]);
            acc[7] = fmaf(pv, f3.y, acc[7]);
        }
        __syncthreads();
    }

    // ---- reductions ----
#pragma unroll
    for (int h = 0; h < HEADS; h++)
#pragma unroll
        for (int d = 16; d; d >>= 1)
            sum[h] += __shfl_xor_sync(0xffffffffu, sum[h], d);
    if (lane == 0)
#pragma unroll
        for (int h = 0; h < HEADS; h++) red_sh[h][wid] = sum[h];
#pragma unroll
    for (int d = 0; d < 8; d++) acc_sh[q][c][d] = acc[d];
    __syncthreads();
    if (t < HEADS) {
        float tt = 0.f;
#pragma unroll
        for (int w = 0; w < 8; w++) tt += red_sh[t][w];
        tot_sh[t] = tt;
    }
    __syncthreads();

    float s = 0.f;
#pragma unroll
    for (int qq = 0; qq < 8; qq++) s += acc_sh[qq][t >> 3][t & 7];
    s *= (1.0f / tot_sh[t >> 6]);
    out[(size_t)row * HD + t] = s;
}

// --------------------------------------------------------------------------
extern "C" void kernel_launch(void* const* d_in, const int* in_sizes, int n_in,
                              void* d_out, int out_size) {
    const float* x     = (const float*)d_in[0];
    const int*   mask  = (const int*)d_in[1];
    const float* W     = (const float*)d_in[2];
    const float* a_src = (const float*)d_in[3];
    const float* a_dst = (const float*)d_in[4];
    float*       out   = (float*)d_out;

    fat_kernel<<<2176, 256>>>(x, W, a_src, a_dst, mask);
    max_sj_kernel<<<1, 256>>>();
    gather_kernel<<<NN, 256>>>(out);
}

// round 9
// speedup vs baseline: 1.0114x; 1.0114x over previous
#include <cuda_runtime.h>
#include <cuda_fp16.h>
#include <math.h>

#define NN      4096
#define IN_DIM  128
#define HEADS   4
#define OUT_DIM 64
#define HD      256   // HEADS*OUT_DIM
#define NB      512   // gather chunk size
#define NBP     (NB + 8)

// persistent scratch (allocation-free rule: __device__ globals)
__device__ uint4          g_hb[NN * 32];           // h in fp16: 4096 x 256 x 2B = 2 MB
__device__ float          g_si[NN * HEADS];
__device__ float          g_sj[NN * HEADS];
__device__ float          g_mx[HEADS];
__device__ unsigned short g_nbr[(size_t)NN * NN];  // padded CSR (contiguous per row)
__device__ int            g_cnt[NN];

// --------------------------------------------------------------------------
// Kernel 1: h = x @ W (fp16 out) + fused per-(node,head) scores. 16 rows/blk.
// --------------------------------------------------------------------------
__global__ __launch_bounds__(256) void gemm_h_kernel(const float* __restrict__ x,
                                                     const float* __restrict__ W,
                                                     const float* __restrict__ a_src,
                                                     const float* __restrict__ a_dst) {
    __shared__ float xs[16][IN_DIM];
    __shared__ float s_si[16][HEADS];
    __shared__ float s_sj[16][HEADS];
    const int t = threadIdx.x;
    const int row0 = blockIdx.x * 16;

    for (int idx = t; idx < 16 * IN_DIM; idx += 256)
        xs[idx >> 7][idx & 127] = x[row0 * IN_DIM + idx];
    if (t < 64) { s_si[t >> 2][t & 3] = 0.f; s_sj[t >> 2][t & 3] = 0.f; }
    __syncthreads();

    const int slot = t & 63;   // float4 column (dims slot*4..+3)
    const int grp  = t >> 6;   // 4 row-groups of 4 rows
    float4 acc[4];
#pragma unroll
    for (int r = 0; r < 4; r++) acc[r] = make_float4(0.f, 0.f, 0.f, 0.f);

    const float4* W4 = (const float4*)W;
#pragma unroll 8
    for (int k = 0; k < IN_DIM; k++) {
        float4 wv = W4[k * 64 + slot];
#pragma unroll
        for (int r = 0; r < 4; r++) {
            float xv = xs[grp * 4 + r][k];
            acc[r].x = fmaf(xv, wv.x, acc[r].x);
            acc[r].y = fmaf(xv, wv.y, acc[r].y);
            acc[r].z = fmaf(xv, wv.z, acc[r].z);
            acc[r].w = fmaf(xv, wv.w, acc[r].w);
        }
    }
    __half2* HB = (__half2*)g_hb;
#pragma unroll
    for (int r = 0; r < 4; r++) {
        int row = row0 + grp * 4 + r;
        HB[(size_t)row * 128 + slot * 2]     = __floats2half2_rn(acc[r].x, acc[r].y);
        HB[(size_t)row * 128 + slot * 2 + 1] = __floats2half2_rn(acc[r].z, acc[r].w);
    }
    const int d0 = (slot * 4) & 63;
    const int hh = slot >> 4;
    float as0 = a_src[d0], as1 = a_src[d0 + 1], as2 = a_src[d0 + 2], as3 = a_src[d0 + 3];
    float ad0 = a_dst[d0], ad1 = a_dst[d0 + 1], ad2 = a_dst[d0 + 2], ad3 = a_dst[d0 + 3];
#pragma unroll
    for (int r = 0; r < 4; r++) {
        float psi = acc[r].x * as0 + acc[r].y * as1 + acc[r].z * as2 + acc[r].w * as3;
        float psj = acc[r].x * ad0 + acc[r].y * ad1 + acc[r].z * ad2 + acc[r].w * ad3;
        atomicAdd(&s_si[grp * 4 + r][hh], psi);
        atomicAdd(&s_sj[grp * 4 + r][hh], psj);
    }
    __syncthreads();
    if (t < 64) {
        g_si[(row0 + (t >> 2)) * HEADS + (t & 3)] = s_si[t >> 2][t & 3];
        g_sj[(row0 + (t >> 2)) * HEADS + (t & 3)] = s_sj[t >> 2][t & 3];
    }
}

// --------------------------------------------------------------------------
// Kernel 2: standalone CSR build (R4 shape: low regs, no smem, occ-friendly).
// 1 warp per row, 8 warps/block, grid 512.
// --------------------------------------------------------------------------
__global__ __launch_bounds__(256) void csr_kernel(const int* __restrict__ mask) {
    const int warp = threadIdx.x >> 5, lane = threadIdx.x & 31;
    const int row  = blockIdx.x * 8 + warp;
    const int4* m4 = (const int4*)mask + (size_t)row * (NN / 4);
    unsigned short* dst = g_nbr + (size_t)row * NN;

    int base = 0;
#pragma unroll 4
    for (int it = 0; it < NN / 128; it++) {          // 32 iters
        int4 v = m4[it * 32 + lane];
        int b0 = (v.x != 0), b1 = (v.y != 0), b2 = (v.z != 0), b3 = (v.w != 0);
        int mycnt = b0 + b1 + b2 + b3;
        int incl = mycnt;
#pragma unroll
        for (int d = 1; d < 32; d <<= 1) {
            int nn = __shfl_up_sync(0xffffffffu, incl, d);
            if (lane >= d) incl += nn;
        }
        int total = __shfl_sync(0xffffffffu, incl, 31);
        int off = incl - mycnt;
        int jb  = (it * 32 + lane) * 4;
        int pos = base + off;
        if (b0) dst[pos++] = (unsigned short)(jb);
        if (b1) dst[pos++] = (unsigned short)(jb + 1);
        if (b2) dst[pos++] = (unsigned short)(jb + 2);
        if (b3) dst[pos++] = (unsigned short)(jb + 3);
        base += total;
    }
    if (lane == 0) g_cnt[row] = base;
}

// --------------------------------------------------------------------------
// Kernel 3: g_mx[h] = max_n g_sj[n][h]. One block.
// --------------------------------------------------------------------------
__global__ __launch_bounds__(256) void max_sj_kernel() {
    __shared__ float red[HEADS][8];
    const int t = threadIdx.x, lane = t & 31, wid = t >> 5;
    float mx[HEADS];
#pragma unroll
    for (int h = 0; h < HEADS; h++) mx[h] = -INFINITY;
    const float4* s4 = (const float4*)g_sj;
    for (int i = t; i < NN; i += 256) {
        float4 v = s4[i];
        mx[0] = fmaxf(mx[0], v.x); mx[1] = fmaxf(mx[1], v.y);
        mx[2] = fmaxf(mx[2], v.z); mx[3] = fmaxf(mx[3], v.w);
    }
#pragma unroll
    for (int h = 0; h < HEADS; h++)
#pragma unroll
        for (int d = 16; d; d >>= 1)
            mx[h] = fmaxf(mx[h], __shfl_xor_sync(0xffffffffu, mx[h], d));
    if (lane == 0)
#pragma unroll
        for (int h = 0; h < HEADS; h++) red[h][wid] = mx[h];
    __syncthreads();
    if (t < HEADS) {
        float m = red[t][0];
#pragma unroll
        for (int w = 1; w < 8; w++) m = fmaxf(m, red[t][w]);
        g_mx[t] = m;
    }
}

// --------------------------------------------------------------------------
// Kernel 4: sparse gather attention (R6 shape, NB=512).
// --------------------------------------------------------------------------
__global__ __launch_bounds__(256) void gather_kernel(float* __restrict__ out) {
    __shared__ unsigned short nbr[NN];          // 8 KB
    __shared__ float p_sh[HEADS][NBP];          // 8.3 KB
    __shared__ float acc_sh[8][32][8];          // 8 KB
    __shared__ float red_sh[HEADS][8];
    __shared__ float tot_sh[HEADS];

    const int t    = threadIdx.x;
    const int lane = t & 31;
    const int wid  = t >> 5;
    const int row  = blockIdx.x;
    const int c    = t & 31;      // 16B chunk of the 512B fp16 row
    const int q    = t >> 5;      // j-subslot (warp)
    const int hc   = c >> 3;      // head owned in acc pass

    int cnt = g_cnt[row];
    const bool uniform = (cnt == 0);
    if (uniform) cnt = NN;
    const unsigned short* nrow = g_nbr + (size_t)row * NN;
    for (int jj = t; jj < cnt; jj += 256)
        nbr[jj] = uniform ? (unsigned short)jj : nrow[jj];

    float si[HEADS], m[HEADS];
#pragma unroll
    for (int h = 0; h < HEADS; h++) {
        si[h] = g_si[row * HEADS + h];
        float v = si[h] + g_mx[h];
        m[h] = fmaxf(v, 0.2f * v);        // lrelu, >= all row scores
    }
    float sum[HEADS] = {0.f, 0.f, 0.f, 0.f};
    float acc[8] = {0.f, 0.f, 0.f, 0.f, 0.f, 0.f, 0.f, 0.f};

    const float4* gsj4 = (const float4*)g_sj;
    __syncthreads();

    for (int base = 0; base < cnt; base += NB) {
        const int cn = min(NB, cnt - base);

        // ---- p-pass ----
        for (int jj = t; jj < cn; jj += 256) {
            float4 sj = gsj4[nbr[base + jj]];
            float e0 = si[0] + sj.x; e0 = fmaxf(e0, 0.2f * e0);
            float e1 = si[1] + sj.y; e1 = fmaxf(e1, 0.2f * e1);
            float e2 = si[2] + sj.z; e2 = fmaxf(e2, 0.2f * e2);
            float e3 = si[3] + sj.w; e3 = fmaxf(e3, 0.2f * e3);
            float p0 = uniform ? 1.f : __expf(e0 - m[0]);
            float p1 = uniform ? 1.f : __expf(e1 - m[1]);
            float p2 = uniform ? 1.f : __expf(e2 - m[2]);
            float p3 = uniform ? 1.f : __expf(e3 - m[3]);
            p_sh[0][jj] = p0; p_sh[1][jj] = p1;
            p_sh[2][jj] = p2; p_sh[3][jj] = p3;
            sum[0] += p0; sum[1] += p1; sum[2] += p2; sum[3] += p3;
        }
        __syncthreads();

        // ---- acc-pass: fp16 h rows, warp covers full 512B row per edge ----
#pragma unroll 8
        for (int jj = q; jj < cn; jj += 8) {
            int j = nbr[base + jj];
            float pv = p_sh[hc][jj];
            uint4 hv = g_hb[(size_t)j * 32 + c];
            float2 f0 = __half22float2(*(__half2*)&hv.x);
            float2 f1 = __half22float2(*(__half2*)&hv.y);
            float2 f2 = __half22float2(*(__half2*)&hv.z);
            float2 f3 = __half22float2(*(__half2*)&hv.w);
            acc[0] = fmaf(pv, f0.x, acc[0]);
            acc[1] = fmaf(pv, f0.y, acc[1]);
            acc[2] = fmaf(pv, f1.x, acc[2]);
            acc[3] = fmaf(pv, f1.y, acc[3]);
            acc[4] = fmaf(pv, f2.x, acc[4]);
            acc[5] = fmaf(pv, f2.y, acc[5]);
            acc[6] = fmaf(pv, f3.x, acc[6]);
            acc[7] = fmaf(pv, f3.y, acc[7]);
        }
        __syncthreads();
    }

    // ---- reductions ----
#pragma unroll
    for (int h = 0; h < HEADS; h++)
#pragma unroll
        for (int d = 16; d; d >>= 1)
            sum[h] += __shfl_xor_sync(0xffffffffu, sum[h], d);
    if (lane == 0)
#pragma unroll
        for (int h = 0; h < HEADS; h++) red_sh[h][wid] = sum[h];
#pragma unroll
    for (int d = 0; d < 8; d++) acc_sh[q][c][d] = acc[d];
    __syncthreads();
    if (t < HEADS) {
        float tt = 0.f;
#pragma unroll
        for (int w = 0; w < 8; w++) tt += red_sh[t][w];
        tot_sh[t] = tt;
    }
    __syncthreads();

    float s = 0.f;
#pragma unroll
    for (int qq = 0; qq < 8; qq++) s += acc_sh[qq][t >> 3][t & 7];
    s *= (1.0f / tot_sh[t >> 6]);
    out[(size_t)row * HD + t] = s;
}

// --------------------------------------------------------------------------
extern "C" void kernel_launch(void* const* d_in, const int* in_sizes, int n_in,
                              void* d_out, int out_size) {
    const float* x     = (const float*)d_in[0];
    const int*   mask  = (const int*)d_in[1];
    const float* W     = (const float*)d_in[2];
    const float* a_src = (const float*)d_in[3];
    const float* a_dst = (const float*)d_in[4];
    float*       out   = (float*)d_out;

    // one-time host-side setup (no device memory involved)
    static cudaStream_t s1 = nullptr;
    static cudaEvent_t  e_fork = nullptr, e_join = nullptr;
    if (s1 == nullptr) {
        cudaStreamCreateWithFlags(&s1, cudaStreamNonBlocking);
        cudaEventCreateWithFlags(&e_fork, cudaEventDisableTiming);
        cudaEventCreateWithFlags(&e_join, cudaEventDisableTiming);
    }

    // fork: csr (DRAM-bound) runs concurrently with gemm (compute-bound)
    cudaEventRecord(e_fork, 0);
    cudaStreamWaitEvent(s1, e_fork, 0);
    csr_kernel<<<NN / 8, 256, 0, s1>>>(mask);

    gemm_h_kernel<<<NN / 16, 256>>>(x, W, a_src, a_dst);
    max_sj_kernel<<<1, 256>>>();

    // join, then gather
    cudaEventRecord(e_join, s1);
    cudaStreamWaitEvent(0, e_join, 0);
    gather_kernel<<<NN, 256>>>(out);
}

// round 10
// speedup vs baseline: 1.1020x; 1.0896x over previous
#include <cuda_runtime.h>
#include <cuda_fp16.h>
#include <math.h>

#define NN      4096
#define IN_DIM  128
#define HEADS   4
#define OUT_DIM 64
#define HD      256   // HEADS*OUT_DIM
#define NB      512   // gather chunk size
#define NBP     (NB + 8)
#define SEG     1024  // csr segment length (ints)

// persistent scratch (allocation-free rule: __device__ globals)
__device__ uint4          g_hb[NN * 32];           // h in fp16: 4096 x 256 x 2B = 2 MB
__device__ float          g_si[NN * HEADS];
__device__ float          g_sj[NN * HEADS];
__device__ float          g_mx[HEADS];
__device__ unsigned short g_nbr[(size_t)NN * NN];  // 4 segments of 1024 per row
__device__ int            g_cnt4[NN * 4];

// --------------------------------------------------------------------------
// Kernel 1: h = x @ W (fp16 out) + fused scores. 16 rows/blk, manual MLP=8.
// --------------------------------------------------------------------------
__global__ __launch_bounds__(256) void gemm_h_kernel(const float* __restrict__ x,
                                                     const float* __restrict__ W,
                                                     const float* __restrict__ a_src,
                                                     const float* __restrict__ a_dst) {
    __shared__ float xs[16][IN_DIM];
    __shared__ float s_si[16][HEADS];
    __shared__ float s_sj[16][HEADS];
    const int t = threadIdx.x;
    const int row0 = blockIdx.x * 16;

    for (int idx = t; idx < 16 * IN_DIM; idx += 256)
        xs[idx >> 7][idx & 127] = x[row0 * IN_DIM + idx];
    if (t < 64) { s_si[t >> 2][t & 3] = 0.f; s_sj[t >> 2][t & 3] = 0.f; }
    __syncthreads();

    const int slot = t & 63;   // float4 column (dims slot*4..+3)
    const int grp  = t >> 6;   // 4 row-groups of 4 rows
    float4 acc[4];
#pragma unroll
    for (int r = 0; r < 4; r++) acc[r] = make_float4(0.f, 0.f, 0.f, 0.f);

    const float4* W4 = (const float4*)W;
#pragma unroll
    for (int kc = 0; kc < IN_DIM; kc += 8) {
        float4 wv[8];
#pragma unroll
        for (int u = 0; u < 8; u++) wv[u] = W4[(kc + u) * 64 + slot];   // MLP=8
#pragma unroll
        for (int u = 0; u < 8; u++) {
#pragma unroll
            for (int r = 0; r < 4; r++) {
                float xv = xs[grp * 4 + r][kc + u];
                acc[r].x = fmaf(xv, wv[u].x, acc[r].x);
                acc[r].y = fmaf(xv, wv[u].y, acc[r].y);
                acc[r].z = fmaf(xv, wv[u].z, acc[r].z);
                acc[r].w = fmaf(xv, wv[u].w, acc[r].w);
            }
        }
    }
    __half2* HB = (__half2*)g_hb;
#pragma unroll
    for (int r = 0; r < 4; r++) {
        int row = row0 + grp * 4 + r;
        HB[(size_t)row * 128 + slot * 2]     = __floats2half2_rn(acc[r].x, acc[r].y);
        HB[(size_t)row * 128 + slot * 2 + 1] = __floats2half2_rn(acc[r].z, acc[r].w);
    }
    const int d0 = (slot * 4) & 63;
    const int hh = slot >> 4;
    float as0 = a_src[d0], as1 = a_src[d0 + 1], as2 = a_src[d0 + 2], as3 = a_src[d0 + 3];
    float ad0 = a_dst[d0], ad1 = a_dst[d0 + 1], ad2 = a_dst[d0 + 2], ad3 = a_dst[d0 + 3];
#pragma unroll
    for (int r = 0; r < 4; r++) {
        float psi = acc[r].x * as0 + acc[r].y * as1 + acc[r].z * as2 + acc[r].w * as3;
        float psj = acc[r].x * ad0 + acc[r].y * ad1 + acc[r].z * ad2 + acc[r].w * ad3;
        atomicAdd(&s_si[grp * 4 + r][hh], psi);
        atomicAdd(&s_sj[grp * 4 + r][hh], psj);
    }
    __syncthreads();
    if (t < 64) {
        g_si[(row0 + (t >> 2)) * HEADS + (t & 3)] = s_si[t >> 2][t & 3];
        g_sj[(row0 + (t >> 2)) * HEADS + (t & 3)] = s_sj[t >> 2][t & 3];
    }
}

// --------------------------------------------------------------------------
// Kernel 2: standalone CSR build, MLP=8. 1 warp = 1 segment of 1024 ints.
// Low footprint: no smem, ~40 regs.
// --------------------------------------------------------------------------
__global__ __launch_bounds__(256) void csr_kernel(const int* __restrict__ mask) {
    const int warp = threadIdx.x >> 5, lane = threadIdx.x & 31;
    const int segIdx = blockIdx.x * 8 + warp;        // 0..16383
    const int row = segIdx >> 2, seg = segIdx & 3;

    const int4* m4 = (const int4*)mask + (size_t)row * (NN / 4) + seg * 256;
    unsigned short* dst = g_nbr + (size_t)row * NN + seg * SEG;

    int4 v[8];
#pragma unroll
    for (int it = 0; it < 8; it++) v[it] = m4[it * 32 + lane];   // MLP=8

    int base = 0;
    const int jb0 = seg * SEG;
#pragma unroll
    for (int it = 0; it < 8; it++) {
        int b0 = (v[it].x != 0), b1 = (v[it].y != 0);
        int b2 = (v[it].z != 0), b3 = (v[it].w != 0);
        int mycnt = b0 + b1 + b2 + b3;
        int incl = mycnt;
#pragma unroll
        for (int d = 1; d < 32; d <<= 1) {
            int nn = __shfl_up_sync(0xffffffffu, incl, d);
            if (lane >= d) incl += nn;
        }
        int total = __shfl_sync(0xffffffffu, incl, 31);
        int off = incl - mycnt;
        int jb  = jb0 + (it * 32 + lane) * 4;
        int pos = base + off;
        if (b0) dst[pos++] = (unsigned short)(jb);
        if (b1) dst[pos++] = (unsigned short)(jb + 1);
        if (b2) dst[pos++] = (unsigned short)(jb + 2);
        if (b3) dst[pos++] = (unsigned short)(jb + 3);
        base += total;
    }
    if (lane == 0) g_cnt4[segIdx] = base;
}

// --------------------------------------------------------------------------
// Kernel 3: g_mx[h] = max_n g_sj[n][h]. One block.
// --------------------------------------------------------------------------
__global__ __launch_bounds__(256) void max_sj_kernel() {
    __shared__ float red[HEADS][8];
    const int t = threadIdx.x, lane = t & 31, wid = t >> 5;
    float mx[HEADS];
#pragma unroll
    for (int h = 0; h < HEADS; h++) mx[h] = -INFINITY;
    const float4* s4 = (const float4*)g_sj;
    for (int i = t; i < NN; i += 256) {
        float4 v = s4[i];
        mx[0] = fmaxf(mx[0], v.x); mx[1] = fmaxf(mx[1], v.y);
        mx[2] = fmaxf(mx[2], v.z); mx[3] = fmaxf(mx[3], v.w);
    }
#pragma unroll
    for (int h = 0; h < HEADS; h++)
#pragma unroll
        for (int d = 16; d; d >>= 1)
            mx[h] = fmaxf(mx[h], __shfl_xor_sync(0xffffffffu, mx[h], d));
    if (lane == 0)
#pragma unroll
        for (int h = 0; h < HEADS; h++) red[h][wid] = mx[h];
    __syncthreads();
    if (t < HEADS) {
        float m = red[t][0];
#pragma unroll
        for (int w = 1; w < 8; w++) m = fmaxf(m, red[t][w]);
        g_mx[t] = m;
    }
}

// --------------------------------------------------------------------------
// Kernel 4: sparse gather attention (NB=512, 4-seg compaction).
// --------------------------------------------------------------------------
__global__ __launch_bounds__(256) void gather_kernel(float* __restrict__ out) {
    __shared__ unsigned short nbr[NN];          // 8 KB
    __shared__ float p_sh[HEADS][NBP];          // 8.3 KB
    __shared__ float acc_sh[8][32][8];          // 8 KB
    __shared__ float red_sh[HEADS][8];
    __shared__ float tot_sh[HEADS];

    const int t    = threadIdx.x;
    const int lane = t & 31;
    const int wid  = t >> 5;
    const int row  = blockIdx.x;
    const int c    = t & 31;      // 16B chunk of the 512B fp16 row
    const int q    = t >> 5;      // j-subslot (warp)
    const int hc   = c >> 3;      // head owned in acc pass

    // ---- stage + compact 4 segments (deterministic order) ----
    int c4[4];
#pragma unroll
    for (int s = 0; s < 4; s++) c4[s] = g_cnt4[row * 4 + s];
    int o1 = c4[0], o2 = o1 + c4[1], o3 = o2 + c4[2];
    int cnt = o3 + c4[3];
    const unsigned short* nrow = g_nbr + (size_t)row * NN;
    const bool uniform = (cnt == 0);
    if (uniform) {
        for (int jj = t; jj < NN; jj += 256) nbr[jj] = (unsigned short)jj;
        cnt = NN;
    } else {
        for (int jj = t; jj < c4[0]; jj += 256) nbr[jj]      = nrow[jj];
        for (int jj = t; jj < c4[1]; jj += 256) nbr[o1 + jj] = nrow[SEG + jj];
        for (int jj = t; jj < c4[2]; jj += 256) nbr[o2 + jj] = nrow[2 * SEG + jj];
        for (int jj = t; jj < c4[3]; jj += 256) nbr[o3 + jj] = nrow[3 * SEG + jj];
    }

    // ---- per-row factors ----
    float si[HEADS], m[HEADS];
#pragma unroll
    for (int h = 0; h < HEADS; h++) {
        si[h] = g_si[row * HEADS + h];
        float v = si[h] + g_mx[h];
        m[h] = fmaxf(v, 0.2f * v);        // lrelu, >= all row scores
    }
    float sum[HEADS] = {0.f, 0.f, 0.f, 0.f};
    float acc[8] = {0.f, 0.f, 0.f, 0.f, 0.f, 0.f, 0.f, 0.f};

    const float4* gsj4 = (const float4*)g_sj;
    __syncthreads();

    for (int base = 0; base < cnt; base += NB) {
        const int cn = min(NB, cnt - base);

        // ---- p-pass ----
        for (int jj = t; jj < cn; jj += 256) {
            float4 sj = gsj4[nbr[base + jj]];
            float e0 = si[0] + sj.x; e0 = fmaxf(e0, 0.2f * e0);
            float e1 = si[1] + sj.y; e1 = fmaxf(e1, 0.2f * e1);
            float e2 = si[2] + sj.z; e2 = fmaxf(e2, 0.2f * e2);
            float e3 = si[3] + sj.w; e3 = fmaxf(e3, 0.2f * e3);
            float p0 = uniform ? 1.f : __expf(e0 - m[0]);
            float p1 = uniform ? 1.f : __expf(e1 - m[1]);
            float p2 = uniform ? 1.f : __expf(e2 - m[2]);
            float p3 = uniform ? 1.f : __expf(e3 - m[3]);
            p_sh[0][jj] = p0; p_sh[1][jj] = p1;
            p_sh[2][jj] = p2; p_sh[3][jj] = p3;
            sum[0] += p0; sum[1] += p1; sum[2] += p2; sum[3] += p3;
        }
        __syncthreads();

        // ---- acc-pass: fp16 h rows, warp covers full 512B row per edge ----
#pragma unroll 8
        for (int jj = q; jj < cn; jj += 8) {
            int j = nbr[base + jj];
            float pv = p_sh[hc][jj];
            uint4 hv = g_hb[(size_t)j * 32 + c];
            float2 f0 = __half22float2(*(__half2*)&hv.x);
            float2 f1 = __half22float2(*(__half2*)&hv.y);
            float2 f2 = __half22float2(*(__half2*)&hv.z);
            float2 f3 = __half22float2(*(__half2*)&hv.w);
            acc[0] = fmaf(pv, f0.x, acc[0]);
            acc[1] = fmaf(pv, f0.y, acc[1]);
            acc[2] = fmaf(pv, f1.x, acc[2]);
            acc[3] = fmaf(pv, f1.y, acc[3]);
            acc[4] = fmaf(pv, f2.x, acc[4]);
            acc[5] = fmaf(pv, f2.y, acc[5]);
            acc[6] = fmaf(pv, f3.x, acc[6]);
            acc[7] = fmaf(pv, f3.y, acc[7]);
        }
        __syncthreads();
    }

    // ---- reductions ----
#pragma unroll
    for (int h = 0; h < HEADS; h++)
#pragma unroll
        for (int d = 16; d; d >>= 1)
            sum[h] += __shfl_xor_sync(0xffffffffu, sum[h], d);
    if (lane == 0)
#pragma unroll
        for (int h = 0; h < HEADS; h++) red_sh[h][wid] = sum[h];
#pragma unroll
    for (int d = 0; d < 8; d++) acc_sh[q][c][d] = acc[d];
    __syncthreads();
    if (t < HEADS) {
        float tt = 0.f;
#pragma unroll
        for (int w = 0; w < 8; w++) tt += red_sh[t][w];
        tot_sh[t] = tt;
    }
    __syncthreads();

    float s = 0.f;
#pragma unroll
    for (int qq = 0; qq < 8; qq++) s += acc_sh[qq][t >> 3][t & 7];
    s *= (1.0f / tot_sh[t >> 6]);
    out[(size_t)row * HD + t] = s;
}

// --------------------------------------------------------------------------
extern "C" void kernel_launch(void* const* d_in, const int* in_sizes, int n_in,
                              void* d_out, int out_size) {
    const float* x     = (const float*)d_in[0];
    const int*   mask  = (const int*)d_in[1];
    const float* W     = (const float*)d_in[2];
    const float* a_src = (const float*)d_in[3];
    const float* a_dst = (const float*)d_in[4];
    float*       out   = (float*)d_out;

    csr_kernel<<<NN * 4 / 8, 256>>>(mask);
    gemm_h_kernel<<<NN / 16, 256>>>(x, W, a_src, a_dst);
    max_sj_kernel<<<1, 256>>>();
    gather_kernel<<<NN, 256>>>(out);
}